// round 3
// baseline (speedup 1.0000x reference)
#include <cuda_runtime.h>
#include <math.h>

#define BN_EPS 1e-5f

// ---------------- scratch (static device globals; no allocations) ----------------
__device__ float g_ybuf[16*1024*16*64];   // 67MB: raw pre-BN activations (max over stages)
__device__ float g_h0[16*4096*32];
__device__ float g_p1[16*1024*3];
__device__ float g_h1[16*1024*64];
__device__ float g_p2[16*256*3];
__device__ float g_h2[16*256*128];
__device__ float g_p3[16*64*3];
__device__ float g_h3[16*64*256];
__device__ float g_p4[16*16*3];
__device__ float g_h4[16*16*512];
__device__ int   g_knn[16*1024*16];
__device__ float g_part[512*2*512];       // [NB=512][2][D<=512]
__device__ float g_scale[512];
__device__ float g_shift[512];

// ---------------- FPS: one block per batch, points in registers ----------------
template<int N, int T>
__global__ void fps_kernel(const float* __restrict__ p, int M, float* __restrict__ newp) {
    constexpr int NPT = N / T;
    const int b = blockIdx.x, tid = threadIdx.x;
    const float* pb = p + (size_t)b * N * 3;
    float lx[NPT], ly[NPT], lz[NPT], md[NPT];
#pragma unroll
    for (int j = 0; j < NPT; j++) {
        int g = j * T + tid;
        lx[j] = pb[g*3+0]; ly[j] = pb[g*3+1]; lz[j] = pb[g*3+2];
        md[j] = INFINITY;
    }
    __shared__ float s_bx, s_by, s_bz;
    __shared__ float s_wd[16];
    __shared__ int   s_wi[16];
    __shared__ int   s_win;
    if (tid == 0) {
        s_bx = pb[0]; s_by = pb[1]; s_bz = pb[2];
        float* o = newp + (size_t)b * M * 3;
        o[0] = pb[0]; o[1] = pb[1]; o[2] = pb[2];
    }
    __syncthreads();
    float bx = s_bx, by = s_by, bz = s_bz;
    const int nw = T / 32;
    for (int t = 1; t < M; t++) {
        float bestd = -1.0f; int besti = N;
#pragma unroll
        for (int j = 0; j < NPT; j++) {
            float dx = lx[j]-bx, dy = ly[j]-by, dz = lz[j]-bz;
            float d = dx*dx + dy*dy + dz*dz;
            float v = fminf(md[j], d);
            md[j] = v;
            int g = j * T + tid;
            if (v > bestd || (v == bestd && g < besti)) { bestd = v; besti = g; }
        }
        // warp reduce (max, lowest index tie-break)
#pragma unroll
        for (int o = 16; o > 0; o >>= 1) {
            float od = __shfl_down_sync(0xffffffffu, bestd, o);
            int   oi = __shfl_down_sync(0xffffffffu, besti, o);
            if (od > bestd || (od == bestd && oi < besti)) { bestd = od; besti = oi; }
        }
        if ((tid & 31) == 0) { s_wd[tid >> 5] = bestd; s_wi[tid >> 5] = besti; }
        __syncthreads();
        if (tid == 0) {
            float bd = s_wd[0]; int bi = s_wi[0];
            for (int w = 1; w < nw; w++)
                if (s_wd[w] > bd || (s_wd[w] == bd && s_wi[w] < bi)) { bd = s_wd[w]; bi = s_wi[w]; }
            s_win = bi;
        }
        __syncthreads();
        int win = s_win;
        if ((win % T) == tid) {
            int slot = win / T;
            float cx = 0.f, cy = 0.f, cz = 0.f;
#pragma unroll
            for (int j = 0; j < NPT; j++) if (j == slot) { cx = lx[j]; cy = ly[j]; cz = lz[j]; }
            s_bx = cx; s_by = cy; s_bz = cz;
            float* o = newp + ((size_t)b * M + t) * 3;
            o[0] = cx; o[1] = cy; o[2] = cz;
        }
        __syncthreads();
        bx = s_bx; by = s_by; bz = s_bz;
    }
}

// ---------------- kNN (16 nearest, lowest-index tie-break): block per query ----------------
__global__ void knn_kernel(const float* __restrict__ p, const float* __restrict__ newp,
                           int N, int M, int* __restrict__ knn) {
    extern __shared__ float dist[];
    __shared__ float wd[4];
    __shared__ int   wi[4];
    const int q = blockIdx.x;
    const int b = q / M;
    const int tid = threadIdx.x;
    const float* pb = p + (size_t)b * N * 3;
    const float qx = newp[q*3+0], qy = newp[q*3+1], qz = newp[q*3+2];
    for (int n = tid; n < N; n += 128) {
        float dx = qx - pb[n*3+0], dy = qy - pb[n*3+1], dz = qz - pb[n*3+2];
        dist[n] = dx*dx + dy*dy + dz*dz;
    }
    __syncthreads();
    for (int r = 0; r < 16; r++) {
        float bd = INFINITY; int bi = N;
        for (int n = tid; n < N; n += 128) {
            float d = dist[n];
            if (d < bd || (d == bd && n < bi)) { bd = d; bi = n; }
        }
#pragma unroll
        for (int o = 16; o > 0; o >>= 1) {
            float od = __shfl_down_sync(0xffffffffu, bd, o);
            int   oi = __shfl_down_sync(0xffffffffu, bi, o);
            if (od < bd || (od == bd && oi < bi)) { bd = od; bi = oi; }
        }
        if ((tid & 31) == 0) { wd[tid >> 5] = bd; wi[tid >> 5] = bi; }
        __syncthreads();
        if (tid == 0) {
            float fbd = wd[0]; int fbi = wi[0];
            for (int w = 1; w < 4; w++)
                if (wd[w] < fbd || (wd[w] == fbd && wi[w] < fbi)) { fbd = wd[w]; fbi = wi[w]; }
            knn[(size_t)q*16 + r] = fbi;
            dist[fbi] = INFINITY;
        }
        __syncthreads();
    }
}

// ---------------- grouped GEMM: y[q,k,d] = feat(q,k,:) . W(:,d) ----------------
__global__ void td_gemm_kernel(const float* __restrict__ p, const float* __restrict__ h,
                               const float* __restrict__ newp, const int* __restrict__ knn,
                               const float* __restrict__ W, int N, int M, int C, int D,
                               float* __restrict__ y) {
    extern __shared__ float feat[];   // 16*(C+3)
    __shared__ int   s_knn[16];
    __shared__ float s_np[3];
    const int q = blockIdx.x;
    const int b = q / M;
    const int t = threadIdx.x;
    if (t < 16) s_knn[t] = knn[(size_t)q*16 + t];
    if (t < 3)  s_np[t]  = newp[q*3 + t];
    __syncthreads();
    const int F = C + 3;
    const float* pb = p + (size_t)b * N * 3;
    const float* hb = h + (size_t)b * N * C;
    for (int e = t; e < 16 * F; e += D) {
        int k = e / F, c = e - k * F;
        int n = s_knn[k];
        feat[e] = (c < 3) ? (pb[n*3 + c] - s_np[c]) : hb[(size_t)n * C + (c - 3)];
    }
    __syncthreads();
    size_t ybase = (size_t)q * 16 * D + t;
    for (int k = 0; k < 16; k++) {
        const float* f = feat + k * F;
        float acc = 0.f;
        for (int c = 0; c < F; c++) acc += f[c] * W[(size_t)c * D + t];
        y[ybase + (size_t)k * D] = acc;
    }
}

// ---------------- deterministic per-channel stats (2-level) ----------------
__global__ void stats_partial(const float* __restrict__ y, int Q, int D, float* __restrict__ part) {
    const int NB = gridDim.x;
    const int rpb = (Q + NB - 1) / NB;
    const int r0 = blockIdx.x * rpb;
    const int r1 = min(r0 + rpb, Q);
    __shared__ float ss[256], sq[256];
    const int tid = threadIdx.x;
    if (D <= 256) {
        const int rpi = 256 / D;
        const int c = tid % D;
        const int ro = tid / D;
        float s = 0.f, q2 = 0.f;
        for (int r = r0 + ro; r < r1; r += rpi) {
            float v = y[(size_t)r * D + c]; s += v; q2 += v * v;
        }
        ss[tid] = s; sq[tid] = q2;
        __syncthreads();
        if (tid < D) {
            for (int o = 1; o < rpi; o++) { s += ss[tid + o*D]; q2 += sq[tid + o*D]; }
            part[(size_t)blockIdx.x * 2 * D + tid]     = s;
            part[(size_t)blockIdx.x * 2 * D + D + tid] = q2;
        }
    } else { // D == 512
        float s0 = 0.f, q0 = 0.f, s1 = 0.f, q1 = 0.f;
        const int c = tid;
        for (int r = r0; r < r1; r++) {
            float v = y[(size_t)r * 512 + c];       s0 += v; q0 += v * v;
            float w = y[(size_t)r * 512 + c + 256]; s1 += w; q1 += w * w;
        }
        size_t base = (size_t)blockIdx.x * 1024;
        part[base + c]             = s0;
        part[base + c + 256]       = s1;
        part[base + 512 + c]       = q0;
        part[base + 512 + c + 256] = q1;
    }
}

__global__ void stats_final(const float* __restrict__ part, int NB, int D, float cnt,
                            const float* __restrict__ g, const float* __restrict__ bta,
                            float* __restrict__ scale, float* __restrict__ shift) {
    const int c = threadIdx.x;
    if (c >= D) return;
    float S = 0.f, Q2 = 0.f;
    for (int i = 0; i < NB; i++) {
        S  += part[(size_t)i * 2 * D + c];
        Q2 += part[(size_t)i * 2 * D + D + c];
    }
    float m = S / cnt;
    float v = Q2 / cnt - m * m;
    float sc = g[c] * rsqrtf(v + BN_EPS);
    scale[c] = sc;
    shift[c] = bta[c] - m * sc;
}

// ---------------- finalize: max over k (sign-aware) + BN + ReLU ----------------
__global__ void td_finalize(const float* __restrict__ y, const float* __restrict__ scale,
                            const float* __restrict__ shift, int Qout, int D,
                            float* __restrict__ hout) {
    int i = blockIdx.x * 256 + threadIdx.x;
    if (i >= Qout * D) return;
    int q = i / D, d = i - q * D;
    const float* yq = y + (size_t)q * 16 * D + d;
    float sc = scale[d];
    float v;
    if (sc >= 0.f) {
        v = -INFINITY;
        for (int k = 0; k < 16; k++) v = fmaxf(v, yq[(size_t)k * D]);
    } else {
        v = INFINITY;
        for (int k = 0; k < 16; k++) v = fminf(v, yq[(size_t)k * D]);
    }
    hout[i] = fmaxf(0.f, sc * v + shift[d]);
}

// ---------------- stage 0: h = p @ W1 (3->32) ----------------
__global__ void s0_gemm(const float* __restrict__ x, const float* __restrict__ W1,
                        float* __restrict__ y) {
    int i = blockIdx.x * 256 + threadIdx.x;
    if (i >= 16*4096*32) return;
    int pt = i >> 5, c = i & 31;
    const float* xp = x + (size_t)pt * 3;
    y[i] = xp[0]*W1[c] + xp[1]*W1[32+c] + xp[2]*W1[64+c];
}

__global__ void normalize_kernel(const float* __restrict__ y, const float* __restrict__ scale,
                                 const float* __restrict__ shift, int total, int D,
                                 float* __restrict__ out) {
    int i = blockIdx.x * 256 + threadIdx.x;
    if (i >= total) return;
    int c = i % D;
    out[i] = fmaxf(0.f, y[i] * scale[c] + shift[c]);
}

// ---------------- classifier head: single block, channel-per-thread ----------------
__global__ void classifier_kernel(const float* __restrict__ h4,
                                  const float* __restrict__ Wc1, const float* __restrict__ bc1,
                                  const float* __restrict__ gc1, const float* __restrict__ hc1,
                                  const float* __restrict__ Wc2, const float* __restrict__ bc2,
                                  const float* __restrict__ gc2, const float* __restrict__ hc2,
                                  const float* __restrict__ Wc3, const float* __restrict__ bc3,
                                  float* __restrict__ out) {
    __shared__ float sb[12288];  // 48KB: z[0..8192), z1[8192..12288), z2 overlays [0..2048)
    float* z  = sb;
    float* z1 = sb + 8192;
    const int t = threadIdx.x;  // 256 threads
    for (int e = t; e < 8192; e += 256) {
        int b = e >> 9, c = e & 511;
        float s = 0.f;
        for (int k = 0; k < 16; k++) s += h4[((size_t)(b*16 + k))*512 + c];
        z[e] = s * (1.f/16.f);
    }
    __syncthreads();
    // layer 1: 512 -> 256
    {
        float acc[16];
#pragma unroll
        for (int b = 0; b < 16; b++) acc[b] = bc1[t];
        for (int i = 0; i < 512; i++) {
            float w = Wc1[(size_t)i*256 + t];
#pragma unroll
            for (int b = 0; b < 16; b++) acc[b] += z[b*512 + i] * w;
        }
        float m = 0.f;
#pragma unroll
        for (int b = 0; b < 16; b++) m += acc[b];
        m *= (1.f/16.f);
        float v = 0.f;
#pragma unroll
        for (int b = 0; b < 16; b++) { float d = acc[b]-m; v += d*d; }
        v *= (1.f/16.f);
        float sc = gc1[t] * rsqrtf(v + BN_EPS);
        float sh = hc1[t] - m * sc;
#pragma unroll
        for (int b = 0; b < 16; b++) z1[b*256 + t] = fmaxf(0.f, acc[b]*sc + sh);
    }
    __syncthreads();
    // layer 2: 256 -> 128 (z no longer needed; z2 overlays sb[0..2048))
    float* z2 = sb;
    if (t < 128) {
        float acc[16];
#pragma unroll
        for (int b = 0; b < 16; b++) acc[b] = bc2[t];
        for (int i = 0; i < 256; i++) {
            float w = Wc2[(size_t)i*128 + t];
#pragma unroll
            for (int b = 0; b < 16; b++) acc[b] += z1[b*256 + i] * w;
        }
        float m = 0.f;
#pragma unroll
        for (int b = 0; b < 16; b++) m += acc[b];
        m *= (1.f/16.f);
        float v = 0.f;
#pragma unroll
        for (int b = 0; b < 16; b++) { float d = acc[b]-m; v += d*d; }
        v *= (1.f/16.f);
        float sc = gc2[t] * rsqrtf(v + BN_EPS);
        float sh = hc2[t] - m * sc;
#pragma unroll
        for (int b = 0; b < 16; b++) z2[b*128 + t] = fmaxf(0.f, acc[b]*sc + sh);
    }
    __syncthreads();
    // layer 3: 128 -> 40
    if (t < 40) {
        float acc[16];
#pragma unroll
        for (int b = 0; b < 16; b++) acc[b] = bc3[t];
        for (int i = 0; i < 128; i++) {
            float w = Wc3[(size_t)i*40 + t];
#pragma unroll
            for (int b = 0; b < 16; b++) acc[b] += z2[b*128 + i] * w;
        }
#pragma unroll
        for (int b = 0; b < 16; b++) out[b*40 + t] = acc[b];
    }
}

// ---------------- driver ----------------
extern "C" void kernel_launch(void* const* d_in, const int* in_sizes, int n_in,
                              void* d_out, int out_size) {
    (void)in_sizes; (void)n_in; (void)out_size;
    const float* x   = (const float*)d_in[0];
    const float* W1  = (const float*)d_in[1];
    const float* g1  = (const float*)d_in[2];
    const float* b1  = (const float*)d_in[3];
    const float* W2  = (const float*)d_in[4];
    const float* g2  = (const float*)d_in[5];
    const float* b2  = (const float*)d_in[6];
    const float* W3  = (const float*)d_in[7];
    const float* g3  = (const float*)d_in[8];
    const float* b3  = (const float*)d_in[9];
    const float* W4  = (const float*)d_in[10];
    const float* g4  = (const float*)d_in[11];
    const float* b4  = (const float*)d_in[12];
    const float* W5  = (const float*)d_in[13];
    const float* g5  = (const float*)d_in[14];
    const float* b5  = (const float*)d_in[15];
    const float* Wc1 = (const float*)d_in[16];
    const float* bc1 = (const float*)d_in[17];
    const float* gc1 = (const float*)d_in[18];
    const float* hc1 = (const float*)d_in[19];
    const float* Wc2 = (const float*)d_in[20];
    const float* bc2 = (const float*)d_in[21];
    const float* gc2 = (const float*)d_in[22];
    const float* hc2 = (const float*)d_in[23];
    const float* Wc3 = (const float*)d_in[24];
    const float* bc3 = (const float*)d_in[25];
    float* out = (float*)d_out;

    float *ybuf, *h0, *p1, *h1, *p2, *h2, *p3, *h3, *p4, *h4, *part, *scale, *shift;
    int* knn;
    cudaGetSymbolAddress((void**)&ybuf,  g_ybuf);
    cudaGetSymbolAddress((void**)&h0,    g_h0);
    cudaGetSymbolAddress((void**)&p1,    g_p1);
    cudaGetSymbolAddress((void**)&h1,    g_h1);
    cudaGetSymbolAddress((void**)&p2,    g_p2);
    cudaGetSymbolAddress((void**)&h2,    g_h2);
    cudaGetSymbolAddress((void**)&p3,    g_p3);
    cudaGetSymbolAddress((void**)&h3,    g_h3);
    cudaGetSymbolAddress((void**)&p4,    g_p4);
    cudaGetSymbolAddress((void**)&h4,    g_h4);
    cudaGetSymbolAddress((void**)&knn,   g_knn);
    cudaGetSymbolAddress((void**)&part,  g_part);
    cudaGetSymbolAddress((void**)&scale, g_scale);
    cudaGetSymbolAddress((void**)&shift, g_shift);

    const int NB = 512;

    // ---- stage 0: h0 = relu(bn(x @ W1)) ----
    s0_gemm<<<(16*4096*32 + 255)/256, 256>>>(x, W1, ybuf);
    stats_partial<<<NB, 256>>>(ybuf, 16*4096, 32, part);
    stats_final<<<1, 512>>>(part, NB, 32, (float)(16*4096), g1, b1, scale, shift);
    normalize_kernel<<<(16*4096*32 + 255)/256, 256>>>(ybuf, scale, shift, 16*4096*32, 32, h0);

    // ---- TD1: 4096 -> 1024, C=32 -> D=64 ----
    fps_kernel<4096, 512><<<16, 512>>>(x, 1024, p1);
    knn_kernel<<<16*1024, 128, 4096*4>>>(x, p1, 4096, 1024, knn);
    td_gemm_kernel<<<16*1024, 64, 16*35*4>>>(x, h0, p1, knn, W2, 4096, 1024, 32, 64, ybuf);
    stats_partial<<<NB, 256>>>(ybuf, 16*1024*16, 64, part);
    stats_final<<<1, 512>>>(part, NB, 64, (float)(16*1024*16), g2, b2, scale, shift);
    td_finalize<<<(16*1024*64 + 255)/256, 256>>>(ybuf, scale, shift, 16*1024, 64, h1);

    // ---- TD2: 1024 -> 256, C=64 -> D=128 ----
    fps_kernel<1024, 256><<<16, 256>>>(p1, 256, p2);
    knn_kernel<<<16*256, 128, 1024*4>>>(p1, p2, 1024, 256, knn);
    td_gemm_kernel<<<16*256, 128, 16*67*4>>>(p1, h1, p2, knn, W3, 1024, 256, 64, 128, ybuf);
    stats_partial<<<NB, 256>>>(ybuf, 16*256*16, 128, part);
    stats_final<<<1, 512>>>(part, NB, 128, (float)(16*256*16), g3, b3, scale, shift);
    td_finalize<<<(16*256*128 + 255)/256, 256>>>(ybuf, scale, shift, 16*256, 128, h2);

    // ---- TD3: 256 -> 64, C=128 -> D=256 ----
    fps_kernel<256, 256><<<16, 256>>>(p2, 64, p3);
    knn_kernel<<<16*64, 128, 256*4>>>(p2, p3, 256, 64, knn);
    td_gemm_kernel<<<16*64, 256, 16*131*4>>>(p2, h2, p3, knn, W4, 256, 64, 128, 256, ybuf);
    stats_partial<<<NB, 256>>>(ybuf, 16*64*16, 256, part);
    stats_final<<<1, 512>>>(part, NB, 256, (float)(16*64*16), g4, b4, scale, shift);
    td_finalize<<<(16*64*256 + 255)/256, 256>>>(ybuf, scale, shift, 16*64, 256, h3);

    // ---- TD4: 64 -> 16, C=256 -> D=512 ----
    fps_kernel<64, 64><<<16, 64>>>(p3, 16, p4);
    knn_kernel<<<16*16, 128, 64*4>>>(p3, p4, 64, 16, knn);
    td_gemm_kernel<<<16*16, 512, 16*259*4>>>(p3, h3, p4, knn, W5, 64, 16, 256, 512, ybuf);
    stats_partial<<<NB, 256>>>(ybuf, 16*16*16, 512, part);
    stats_final<<<1, 512>>>(part, NB, 512, (float)(16*16*16), g5, b5, scale, shift);
    td_finalize<<<(16*16*512 + 255)/256, 256>>>(ybuf, scale, shift, 16*16, 512, h4);

    // ---- classifier head ----
    classifier_kernel<<<1, 256>>>(h4, Wc1, bc1, gc1, hc1, Wc2, bc2, gc2, hc2, Wc3, bc3, out);
}

// round 4
// speedup vs baseline: 2.0765x; 2.0765x over previous
#include <cuda_runtime.h>
#include <math.h>

#define BN_EPS 1e-5f

// ---------------- scratch (static device globals; no allocations) ----------------
__device__ float g_ybuf[16*1024*16*64];   // carved: stage0 ybuf | ymax | ymin | part | part2
__device__ float g_h0[16*4096*32];
__device__ float g_p1[16*1024*3];
__device__ float g_h1[16*1024*64];
__device__ float g_p2[16*256*3];
__device__ float g_h2[16*256*128];
__device__ float g_p3[16*64*3];
__device__ float g_h3[16*64*256];
__device__ float g_p4[16*16*3];
__device__ float g_h4[16*16*512];
__device__ int   g_knn[16*1024*16];
__device__ float g_part[512*2*512];       // stage0 partials [NB][2][D]
__device__ float g_scale[512];
__device__ float g_shift[512];

// ---------------- FPS: one block per batch, points in registers, REDUX argmax ----------------
template<int N, int T>
__global__ void fps_kernel(const float* __restrict__ p, int M, float* __restrict__ newp) {
    constexpr int NPT = N / T;
    constexpr int NW  = T / 32;
    const int b = blockIdx.x, tid = threadIdx.x;
    const float* pb = p + (size_t)b * N * 3;
    float lx[NPT], ly[NPT], lz[NPT], md[NPT];
#pragma unroll
    for (int j = 0; j < NPT; j++) {
        int g = j * T + tid;
        lx[j] = pb[g*3+0]; ly[j] = pb[g*3+1]; lz[j] = pb[g*3+2];
        md[j] = INFINITY;
    }
    __shared__ unsigned s_wd[16];
    __shared__ int      s_wi[16];
    __shared__ float    s_b[3];
    if (tid == 0) {
        s_b[0] = pb[0]; s_b[1] = pb[1]; s_b[2] = pb[2];
        float* o = newp + (size_t)b * M * 3;
        o[0] = pb[0]; o[1] = pb[1]; o[2] = pb[2];
    }
    __syncthreads();
    float bx = s_b[0], by = s_b[1], bz = s_b[2];
    for (int t = 1; t < M; t++) {
        // local update + argmax (first-index tie-break via sentinel init)
        float best = 0.0f; int besti = 0x7fffffff;
#pragma unroll
        for (int j = 0; j < NPT; j++) {
            float dx = lx[j]-bx, dy = ly[j]-by, dz = lz[j]-bz;
            float d = dx*dx + dy*dy + dz*dz;
            float v = fminf(md[j], d);
            md[j] = v;
            int g = j * T + tid;
            if (v > best || (v == best && g < besti)) { best = v; besti = g; }
        }
        // warp argmax via REDUX (dists >= 0 so float bits are order-preserving)
        unsigned bb = __float_as_uint(best);
        unsigned mb = __reduce_max_sync(0xffffffffu, bb);
        int cand = (bb == mb) ? besti : 0x7fffffff;
        int wbi = __reduce_min_sync(0xffffffffu, cand);
        if ((tid & 31) == 0) { s_wd[tid >> 5] = mb; s_wi[tid >> 5] = wbi; }
        __syncthreads();
        if (tid < 32) {
            unsigned u = (tid < NW) ? s_wd[tid] : 0u;
            int      ii = (tid < NW) ? s_wi[tid] : 0x7fffffff;
            unsigned m2 = __reduce_max_sync(0xffffffffu, u);
            int c2 = (u == m2) ? ii : 0x7fffffff;
            int win = __reduce_min_sync(0xffffffffu, c2);
            if (tid == 0) {
                const float* wp = pb + (size_t)win * 3;   // L1-hot (48KB, warmed at init)
                float cx = wp[0], cy = wp[1], cz = wp[2];
                s_b[0] = cx; s_b[1] = cy; s_b[2] = cz;
                float* o = newp + ((size_t)b * M + t) * 3;
                o[0] = cx; o[1] = cy; o[2] = cz;
            }
        }
        __syncthreads();
        bx = s_b[0]; by = s_b[1]; bz = s_b[2];
    }
}

// ---------------- kNN: cached per-thread minima, one owner rescan per round ----------------
__global__ void knn_kernel(const float* __restrict__ p, const float* __restrict__ newp,
                           int N, int M, int* __restrict__ knn) {
    extern __shared__ float dist[];          // N floats
    __shared__ float s_tmin[128];
    __shared__ int   s_tidx[128];
    __shared__ int   s_win;
    const int q = blockIdx.x;
    const int b = q / M;
    const int tid = threadIdx.x;
    const float* pb = p + (size_t)b * N * 3;
    const float qx = newp[q*3+0], qy = newp[q*3+1], qz = newp[q*3+2];
    float bd = INFINITY; int bi = 0x7fffffff;
    for (int n = tid; n < N; n += 128) {
        float dx = qx - pb[n*3+0], dy = qy - pb[n*3+1], dz = qz - pb[n*3+2];
        float d = dx*dx + dy*dy + dz*dz;
        dist[n] = d;
        if (d < bd) { bd = d; bi = n; }      // ascending n -> first-index ties
    }
    s_tmin[tid] = bd; s_tidx[tid] = bi;
    __syncthreads();
    for (int r = 0; ; r++) {
        if (tid < 32) {
            float m0 = s_tmin[tid]; int i0 = s_tidx[tid];
#pragma unroll
            for (int off = 32; off < 128; off += 32) {
                float mm = s_tmin[tid + off]; int ii = s_tidx[tid + off];
                if (mm < m0 || (mm == m0 && ii < i0)) { m0 = mm; i0 = ii; }
            }
            unsigned b0 = __float_as_uint(m0);
            unsigned mb = __reduce_min_sync(0xffffffffu, b0);
            int cand = (b0 == mb) ? i0 : 0x7fffffff;
            int win = __reduce_min_sync(0xffffffffu, cand);
            if (tid == 0) { knn[(size_t)q*16 + r] = win; s_win = win; }
        }
        __syncthreads();
        if (r == 15) break;
        int win = s_win;
        if ((win & 127) == tid) {            // owner rescans its slice
            dist[win] = INFINITY;
            float nb = INFINITY; int ni = 0x7fffffff;
            for (int n = tid; n < N; n += 128) {
                float d = dist[n];
                if (d < nb) { nb = d; ni = n; }
            }
            s_tmin[tid] = nb; s_tidx[tid] = ni;
        }
        __syncthreads();
    }
}

// ---------------- fused grouped GEMM + max/min over k + per-block channel stats ----------------
__global__ void td_gemm_fused(const float* __restrict__ p, const float* __restrict__ h,
                              const float* __restrict__ newp, const int* __restrict__ knn,
                              const float* __restrict__ W, int N, int M, int C, int D,
                              float* __restrict__ ymax, float* __restrict__ ymin,
                              float* __restrict__ part) {
    extern __shared__ float feat[];          // 16*(C+3)
    __shared__ int   s_knn[16];
    __shared__ float s_np[3];
    const int q = blockIdx.x;
    const int b = q / M;
    const int t = threadIdx.x;               // D threads, one per output channel
    if (t < 16) s_knn[t] = knn[(size_t)q*16 + t];
    if (t < 3)  s_np[t]  = newp[q*3 + t];
    __syncthreads();
    const int F = C + 3;
    const float* pb = p + (size_t)b * N * 3;
    const float* hb = h + (size_t)b * N * C;
    for (int e = t; e < 16 * F; e += D) {
        int k = e / F, c = e - k * F;
        int n = s_knn[k];
        feat[e] = (c < 3) ? (pb[n*3 + c] - s_np[c]) : hb[(size_t)n * C + (c - 3)];
    }
    __syncthreads();
    float acc[16];
#pragma unroll
    for (int k = 0; k < 16; k++) acc[k] = 0.f;
#pragma unroll 2
    for (int c = 0; c < F; c++) {
        float w = W[(size_t)c * D + t];      // loaded once per c (was 16x)
#pragma unroll
        for (int k = 0; k < 16; k++) acc[k] += feat[k*F + c] * w;   // LDS broadcast
    }
    float mx = -INFINITY, mn = INFINITY, s = 0.f, s2 = 0.f;
#pragma unroll
    for (int k = 0; k < 16; k++) {
        float v = acc[k];
        mx = fmaxf(mx, v); mn = fminf(mn, v);
        s += v; s2 += v * v;
    }
    ymax[(size_t)q * D + t] = mx;
    ymin[(size_t)q * D + t] = mn;
    part[(size_t)q * 2 * D + t]     = s;
    part[(size_t)q * 2 * D + D + t] = s2;
}

// ---------------- stats tree: level-1 reduce of per-block partials ----------------
__global__ void stats_reduce(const float* __restrict__ part, int Q, int D,
                             float* __restrict__ out) {
    const int t = threadIdx.x;               // D threads
    const int per = (Q + gridDim.x - 1) / gridDim.x;
    const int r0 = blockIdx.x * per;
    const int r1 = min(r0 + per, Q);
    float s = 0.f, s2 = 0.f;
    for (int r = r0; r < r1; r++) {
        s  += part[(size_t)r * 2 * D + t];
        s2 += part[(size_t)r * 2 * D + D + t];
    }
    out[(size_t)blockIdx.x * 2 * D + t]     = s;
    out[(size_t)blockIdx.x * 2 * D + D + t] = s2;
}

__global__ void stats_final(const float* __restrict__ part, int NB, int D, float cnt,
                            const float* __restrict__ g, const float* __restrict__ bta,
                            float* __restrict__ scale, float* __restrict__ shift) {
    const int c = threadIdx.x;
    if (c >= D) return;
    float S = 0.f, Q2 = 0.f;
    for (int i = 0; i < NB; i++) {
        S  += part[(size_t)i * 2 * D + c];
        Q2 += part[(size_t)i * 2 * D + D + c];
    }
    float m = S / cnt;
    float v = Q2 / cnt - m * m;
    float sc = g[c] * rsqrtf(v + BN_EPS);
    scale[c] = sc;
    shift[c] = bta[c] - m * sc;
}

// ---------------- apply BN+ReLU to the sign-appropriate extremum ----------------
__global__ void td_norm(const float* __restrict__ ymax, const float* __restrict__ ymin,
                        const float* __restrict__ scale, const float* __restrict__ shift,
                        int total, int D, float* __restrict__ hout) {
    int i = blockIdx.x * 256 + threadIdx.x;
    if (i >= total) return;
    int d = i % D;
    float sc = scale[d];
    float v = (sc >= 0.f) ? ymax[i] : ymin[i];
    hout[i] = fmaxf(0.f, sc * v + shift[d]);
}

// ---------------- stage 0: h = p @ W1 (3->32) ----------------
__global__ void s0_gemm(const float* __restrict__ x, const float* __restrict__ W1,
                        float* __restrict__ y) {
    int i = blockIdx.x * 256 + threadIdx.x;
    if (i >= 16*4096*32) return;
    int pt = i >> 5, c = i & 31;
    const float* xp = x + (size_t)pt * 3;
    y[i] = xp[0]*W1[c] + xp[1]*W1[32+c] + xp[2]*W1[64+c];
}

__global__ void stats_partial(const float* __restrict__ y, int Q, int D, float* __restrict__ part) {
    const int NB = gridDim.x;
    const int rpb = (Q + NB - 1) / NB;
    const int r0 = blockIdx.x * rpb;
    const int r1 = min(r0 + rpb, Q);
    __shared__ float ss[256], sq[256];
    const int tid = threadIdx.x;
    const int rpi = 256 / D;
    const int c = tid % D;
    const int ro = tid / D;
    float s = 0.f, q2 = 0.f;
    for (int r = r0 + ro; r < r1; r += rpi) {
        float v = y[(size_t)r * D + c]; s += v; q2 += v * v;
    }
    ss[tid] = s; sq[tid] = q2;
    __syncthreads();
    if (tid < D) {
        for (int o = 1; o < rpi; o++) { s += ss[tid + o*D]; q2 += sq[tid + o*D]; }
        part[(size_t)blockIdx.x * 2 * D + tid]     = s;
        part[(size_t)blockIdx.x * 2 * D + D + tid] = q2;
    }
}

__global__ void normalize_kernel(const float* __restrict__ y, const float* __restrict__ scale,
                                 const float* __restrict__ shift, int total, int D,
                                 float* __restrict__ out) {
    int i = blockIdx.x * 256 + threadIdx.x;
    if (i >= total) return;
    int c = i % D;
    out[i] = fmaxf(0.f, y[i] * scale[c] + shift[c]);
}

// ---------------- classifier head: single block, channel-per-thread ----------------
__global__ void classifier_kernel(const float* __restrict__ h4,
                                  const float* __restrict__ Wc1, const float* __restrict__ bc1,
                                  const float* __restrict__ gc1, const float* __restrict__ hc1,
                                  const float* __restrict__ Wc2, const float* __restrict__ bc2,
                                  const float* __restrict__ gc2, const float* __restrict__ hc2,
                                  const float* __restrict__ Wc3, const float* __restrict__ bc3,
                                  float* __restrict__ out) {
    __shared__ float sb[12288];
    float* z  = sb;
    float* z1 = sb + 8192;
    const int t = threadIdx.x;  // 256 threads
    for (int e = t; e < 8192; e += 256) {
        int b = e >> 9, c = e & 511;
        float s = 0.f;
        for (int k = 0; k < 16; k++) s += h4[((size_t)(b*16 + k))*512 + c];
        z[e] = s * (1.f/16.f);
    }
    __syncthreads();
    {
        float acc[16];
#pragma unroll
        for (int b = 0; b < 16; b++) acc[b] = bc1[t];
        for (int i = 0; i < 512; i++) {
            float w = Wc1[(size_t)i*256 + t];
#pragma unroll
            for (int b = 0; b < 16; b++) acc[b] += z[b*512 + i] * w;
        }
        float m = 0.f;
#pragma unroll
        for (int b = 0; b < 16; b++) m += acc[b];
        m *= (1.f/16.f);
        float v = 0.f;
#pragma unroll
        for (int b = 0; b < 16; b++) { float d = acc[b]-m; v += d*d; }
        v *= (1.f/16.f);
        float sc = gc1[t] * rsqrtf(v + BN_EPS);
        float sh = hc1[t] - m * sc;
#pragma unroll
        for (int b = 0; b < 16; b++) z1[b*256 + t] = fmaxf(0.f, acc[b]*sc + sh);
    }
    __syncthreads();
    float* z2 = sb;
    if (t < 128) {
        float acc[16];
#pragma unroll
        for (int b = 0; b < 16; b++) acc[b] = bc2[t];
        for (int i = 0; i < 256; i++) {
            float w = Wc2[(size_t)i*128 + t];
#pragma unroll
            for (int b = 0; b < 16; b++) acc[b] += z1[b*256 + i] * w;
        }
        float m = 0.f;
#pragma unroll
        for (int b = 0; b < 16; b++) m += acc[b];
        m *= (1.f/16.f);
        float v = 0.f;
#pragma unroll
        for (int b = 0; b < 16; b++) { float d = acc[b]-m; v += d*d; }
        v *= (1.f/16.f);
        float sc = gc2[t] * rsqrtf(v + BN_EPS);
        float sh = hc2[t] - m * sc;
#pragma unroll
        for (int b = 0; b < 16; b++) z2[b*128 + t] = fmaxf(0.f, acc[b]*sc + sh);
    }
    __syncthreads();
    if (t < 40) {
        float acc[16];
#pragma unroll
        for (int b = 0; b < 16; b++) acc[b] = bc3[t];
        for (int i = 0; i < 128; i++) {
            float w = Wc3[(size_t)i*40 + t];
#pragma unroll
            for (int b = 0; b < 16; b++) acc[b] += z2[b*128 + i] * w;
        }
#pragma unroll
        for (int b = 0; b < 16; b++) out[b*40 + t] = acc[b];
    }
}

// ---------------- driver ----------------
extern "C" void kernel_launch(void* const* d_in, const int* in_sizes, int n_in,
                              void* d_out, int out_size) {
    (void)in_sizes; (void)n_in; (void)out_size;
    const float* x   = (const float*)d_in[0];
    const float* W1  = (const float*)d_in[1];
    const float* g1  = (const float*)d_in[2];
    const float* b1  = (const float*)d_in[3];
    const float* W2  = (const float*)d_in[4];
    const float* g2  = (const float*)d_in[5];
    const float* b2  = (const float*)d_in[6];
    const float* W3  = (const float*)d_in[7];
    const float* g3  = (const float*)d_in[8];
    const float* b3  = (const float*)d_in[9];
    const float* W4  = (const float*)d_in[10];
    const float* g4  = (const float*)d_in[11];
    const float* b4  = (const float*)d_in[12];
    const float* W5  = (const float*)d_in[13];
    const float* g5  = (const float*)d_in[14];
    const float* b5  = (const float*)d_in[15];
    const float* Wc1 = (const float*)d_in[16];
    const float* bc1 = (const float*)d_in[17];
    const float* gc1 = (const float*)d_in[18];
    const float* hc1 = (const float*)d_in[19];
    const float* Wc2 = (const float*)d_in[20];
    const float* bc2 = (const float*)d_in[21];
    const float* gc2 = (const float*)d_in[22];
    const float* hc2 = (const float*)d_in[23];
    const float* Wc3 = (const float*)d_in[24];
    const float* bc3 = (const float*)d_in[25];
    float* out = (float*)d_out;

    float *ybuf, *h0, *p1, *h1, *p2, *h2, *p3, *h3, *p4, *h4, *part0, *scale, *shift;
    int* knn;
    cudaGetSymbolAddress((void**)&ybuf,  g_ybuf);
    cudaGetSymbolAddress((void**)&h0,    g_h0);
    cudaGetSymbolAddress((void**)&p1,    g_p1);
    cudaGetSymbolAddress((void**)&h1,    g_h1);
    cudaGetSymbolAddress((void**)&p2,    g_p2);
    cudaGetSymbolAddress((void**)&h2,    g_h2);
    cudaGetSymbolAddress((void**)&p3,    g_p3);
    cudaGetSymbolAddress((void**)&h3,    g_h3);
    cudaGetSymbolAddress((void**)&p4,    g_p4);
    cudaGetSymbolAddress((void**)&h4,    g_h4);
    cudaGetSymbolAddress((void**)&knn,   g_knn);
    cudaGetSymbolAddress((void**)&part0, g_part);
    cudaGetSymbolAddress((void**)&scale, g_scale);
    cudaGetSymbolAddress((void**)&shift, g_shift);

    // carve scratch from ybuf (temporally disjoint with stage0's use of ybuf[0..2M))
    float* ymax  = ybuf;                       // <= 1,048,576 floats
    float* ymin  = ybuf + 1048576;
    float* part  = ybuf + 2097152;             // <= 2,097,152 floats (TD1)
    float* part2 = ybuf + 4194304;             // <= 65,536 floats
    const int NR = 64;

    // ---- stage 0: h0 = relu(bn(x @ W1)) ----
    s0_gemm<<<(16*4096*32 + 255)/256, 256>>>(x, W1, ybuf);
    stats_partial<<<512, 256>>>(ybuf, 16*4096, 32, part0);
    stats_final<<<1, 32>>>(part0, 512, 32, (float)(16*4096), g1, b1, scale, shift);
    normalize_kernel<<<(16*4096*32 + 255)/256, 256>>>(ybuf, scale, shift, 16*4096*32, 32, h0);

    // ---- TD1: 4096 -> 1024, C=32 -> D=64 ----
    fps_kernel<4096, 512><<<16, 512>>>(x, 1024, p1);
    knn_kernel<<<16*1024, 128, 4096*4>>>(x, p1, 4096, 1024, knn);
    td_gemm_fused<<<16*1024, 64, 16*35*4>>>(x, h0, p1, knn, W2, 4096, 1024, 32, 64, ymax, ymin, part);
    stats_reduce<<<NR, 64>>>(part, 16*1024, 64, part2);
    stats_final<<<1, 64>>>(part2, NR, 64, (float)(16*1024*16), g2, b2, scale, shift);
    td_norm<<<(16*1024*64 + 255)/256, 256>>>(ymax, ymin, scale, shift, 16*1024*64, 64, h1);

    // ---- TD2: 1024 -> 256, C=64 -> D=128 ----
    fps_kernel<1024, 256><<<16, 256>>>(p1, 256, p2);
    knn_kernel<<<16*256, 128, 1024*4>>>(p1, p2, 1024, 256, knn);
    td_gemm_fused<<<16*256, 128, 16*67*4>>>(p1, h1, p2, knn, W3, 1024, 256, 64, 128, ymax, ymin, part);
    stats_reduce<<<NR, 128>>>(part, 16*256, 128, part2);
    stats_final<<<1, 128>>>(part2, NR, 128, (float)(16*256*16), g3, b3, scale, shift);
    td_norm<<<(16*256*128 + 255)/256, 256>>>(ymax, ymin, scale, shift, 16*256*128, 128, h2);

    // ---- TD3: 256 -> 64, C=128 -> D=256 ----
    fps_kernel<256, 256><<<16, 256>>>(p2, 64, p3);
    knn_kernel<<<16*64, 128, 256*4>>>(p2, p3, 256, 64, knn);
    td_gemm_fused<<<16*64, 256, 16*131*4>>>(p2, h2, p3, knn, W4, 256, 64, 128, 256, ymax, ymin, part);
    stats_reduce<<<NR, 256>>>(part, 16*64, 256, part2);
    stats_final<<<1, 256>>>(part2, NR, 256, (float)(16*64*16), g4, b4, scale, shift);
    td_norm<<<(16*64*256 + 255)/256, 256>>>(ymax, ymin, scale, shift, 16*64*256, 256, h3);

    // ---- TD4: 64 -> 16, C=256 -> D=512 ----
    fps_kernel<64, 64><<<16, 64>>>(p3, 16, p4);
    knn_kernel<<<16*16, 128, 64*4>>>(p3, p4, 64, 16, knn);
    td_gemm_fused<<<16*16, 512, 16*259*4>>>(p3, h3, p4, knn, W5, 64, 16, 256, 512, ymax, ymin, part);
    stats_reduce<<<NR, 512>>>(part, 16*16, 512, part2);
    stats_final<<<1, 512>>>(part2, NR, 512, (float)(16*16*16), g5, b5, scale, shift);
    td_norm<<<(16*16*512 + 255)/256, 256>>>(ymax, ymin, scale, shift, 16*16*512, 512, h4);

    // ---- classifier head ----
    classifier_kernel<<<1, 256>>>(h4, Wc1, bc1, gc1, hc1, Wc2, bc2, gc2, hc2, Wc3, bc3, out);
}